// round 9
// baseline (speedup 1.0000x reference)
#include <cuda_runtime.h>

#define BS    2048
#define NINP  512
#define NHID  512
#define TT    8
#define MM    32
#define NTOT  32768
#define GI_COLS 768
#define NPAIR (NTOT/2)   // 16384

#define XSTR (BS*NINP)        // 1048576
#define WSTR (GI_COLS*NINP)   // 393216

typedef unsigned long long u64;
typedef unsigned int u32;

// device scratch
__device__ float g_gi[BS * GI_COLS];       // 6 MB
__device__ float g_hn[TT * NTOT * MM];     // 32 MB
__device__ float g_lg[NTOT * TT];          // 1 MB
__device__ float g_xs[3 * XSTR];           // tf32 splits of x, permuted, 12 MB
__device__ float g_ws[3 * WSTR];           // tf32 splits of W_ih, permuted, 4.5 MB

// ---- packed f32x2 helpers (gates kernel) -----------------------------------
__device__ __forceinline__ void fma2(u64& acc, u64 a, u64 b) {
    asm("fma.rn.f32x2 %0, %1, %2, %0;" : "+l"(acc) : "l"(a), "l"(b));
}
__device__ __forceinline__ u64 pk(float lo, float hi) {
    u64 r; asm("mov.b64 %0, {%1, %2};" : "=l"(r) : "f"(lo), "f"(hi)); return r;
}
__device__ __forceinline__ void unpk(float& lo, float& hi, u64 v) {
    asm("mov.b64 {%0, %1}, %2;" : "=f"(lo), "=f"(hi) : "l"(v));
}
__device__ __forceinline__ float hadd(u64 v) {
    float a, b; unpk(a, b, v); return a + b;
}

// ---- tf32 / mma helpers ----------------------------------------------------
__device__ __forceinline__ float tf32_rn(float x) {
    u32 r; asm("cvt.rna.tf32.f32 %0, %1;" : "=r"(r) : "f"(x));
    return __uint_as_float(r);
}
__device__ __forceinline__ void cpa16(void* dst, const void* src) {
    u32 d = (u32)__cvta_generic_to_shared(dst);
    asm volatile("cp.async.cg.shared.global [%0], [%1], 16;" :: "r"(d), "l"(src));
}
__device__ __forceinline__ void mma_tf32(float* d, const u32* a, const u32* b) {
    asm("mma.sync.aligned.m16n8k8.row.col.f32.tf32.tf32.f32 "
        "{%0,%1,%2,%3},{%4,%5,%6,%7},{%8,%9},{%0,%1,%2,%3};"
        : "+f"(d[0]), "+f"(d[1]), "+f"(d[2]), "+f"(d[3])
        : "r"(a[0]), "r"(a[1]), "r"(a[2]), "r"(a[3]), "r"(b[0]), "r"(b[1]));
}

// ---------------------------------------------------------------------------
// Kernel 0: split fp32 -> 3x tf32 planes, permuted (k, k+4) -> (2c, 2c+1)
// within each k8 group (mma pair layout). One thread per k8 group.
// ---------------------------------------------------------------------------
__global__ void __launch_bounds__(256) convert_split_kernel(
    const float* __restrict__ src, float* __restrict__ dst,
    int term_stride, int ngroups)
{
    int i = blockIdx.x * 256 + threadIdx.x;
    if (i >= ngroups) return;
    const float4* s = (const float4*)(src + (size_t)i * 8);
    float4 v0 = s[0], v1 = s[1];
    float a[8] = {v0.x, v0.y, v0.z, v0.w, v1.x, v1.y, v1.z, v1.w};
    float t1[8], t2[8], t3[8];
#pragma unroll
    for (int j = 0; j < 8; j++) {
        t1[j] = tf32_rn(a[j]);
        float r = a[j] - t1[j];
        t2[j] = tf32_rn(r);
        t3[j] = tf32_rn(r - t2[j]);
    }
    float2* d1 = (float2*)(dst + (size_t)i * 8);
    float2* d2 = (float2*)(dst + term_stride + (size_t)i * 8);
    float2* d3 = (float2*)(dst + 2 * (size_t)term_stride + (size_t)i * 8);
#pragma unroll
    for (int c = 0; c < 4; c++) {
        d1[c] = make_float2(t1[c], t1[c + 4]);
        d2[c] = make_float2(t2[c], t2[c + 4]);
        d3[c] = make_float2(t3[c], t3[c + 4]);
    }
}

// ---------------------------------------------------------------------------
// Kernel 1: gi = x @ W_ih^T + b_ih via mma.sync tf32, 6 split-product terms.
// 64x64 tile, 4 warps (32x32 each). K_CHUNK=32, TRIPLE-buffered cp.async with
// prefetch distance 2 (covers L2 latency). Same k-order as before -> gi is
// bit-identical to the verified version.
// ---------------------------------------------------------------------------
#define ABUF 1152            // 32 rows... no: 64 rows * 18?  -> 64*36/2
#undef ABUF
#define ABUF2 2304           // 64 rows * 36 floats (32-k chunk, stride 36)
#define GSM  ((6*ABUF2 + 64) * 4)   // 3 bufs * (A+B) + bias = ~55.5 KB

__global__ void __launch_bounds__(128, 3) mma_gi_kernel(
    const float* __restrict__ bias)
{
    extern __shared__ float smg[];
    float* As  = smg;                 // [3][ABUF2]
    float* Bsb = smg + 3 * ABUF2;     // [3][ABUF2]
    float* bsm = smg + 6 * ABUF2;     // 64

    const int tid  = threadIdx.x;
    const int lane = tid & 31;
    const int wid  = tid >> 5;
    const int m0   = blockIdx.y * 64;
    const int n0   = blockIdx.x * 64;
    const int wm0  = (wid & 1) * 32;
    const int wn0  = (wid >> 1) * 32;

    if (tid < 16) ((float4*)bsm)[tid] = ((const float4*)(bias + n0))[tid];

    float acc[2][4][4];
#pragma unroll
    for (int mt = 0; mt < 2; mt++)
#pragma unroll
        for (int nt = 0; nt < 4; nt++)
#pragma unroll
            for (int q = 0; q < 4; q++) acc[mt][nt][q] = 0.f;

    // term schedule: pass -> (a_term, b_term); same order as verified version
    #define PA(p) ((0x201100 >> (4*(p))) & 0xF)
    #define PB(p) ((0x021010 >> (4*(p))) & 0xF)

    // chunk c (0..95): pass = c>>4, kc = c&15, covers k = kc*32 .. kc*32+31
    #define STAGE(c, buf) {                                                   \
        const int pass_ = (c) >> 4, kc_ = (c) & 15;                           \
        const float* ap_ = g_xs + (size_t)PA(pass_) * XSTR + (size_t)m0 * 512;\
        const float* bp_ = g_ws + (size_t)PB(pass_) * WSTR + (size_t)n0 * 512;\
        _Pragma("unroll")                                                     \
        for (int i_ = 0; i_ < 4; i_++) {                                      \
            int idx_ = tid + 128 * i_;                                        \
            int r_ = idx_ >> 3, j_ = (idx_ & 7) * 4;                          \
            cpa16(As  + (buf) * ABUF2 + r_ * 36 + j_,                         \
                  ap_ + r_ * 512 + kc_ * 32 + j_);                            \
            cpa16(Bsb + (buf) * ABUF2 + r_ * 36 + j_,                         \
                  bp_ + r_ * 512 + kc_ * 32 + j_);                            \
        }                                                                     \
        asm volatile("cp.async.commit_group;");                               \
    }

    STAGE(0, 0);
    STAGE(1, 1);

    const int aoffl = (lane >> 2) * 36 + (lane & 3) * 2;

#pragma unroll 1
    for (int c = 0; c < 96; c++) {
        const int buf = c % 3;
        asm volatile("cp.async.wait_group 1;");
        __syncthreads();
        if (c < 94) {
            STAGE(c + 2, (c + 2) % 3);
        } else {
            asm volatile("cp.async.commit_group;");   // keep wait invariant
        }

        const float* Ab = As  + buf * ABUF2;
        const float* Bb = Bsb + buf * ABUF2;
#pragma unroll
        for (int kg = 0; kg < 4; kg++) {
            u32 af[2][4];
#pragma unroll
            for (int mt = 0; mt < 2; mt++) {
                uint2 lo = *(const uint2*)(Ab + (wm0 + mt*16)     * 36 + aoffl + kg*8);
                uint2 hi = *(const uint2*)(Ab + (wm0 + mt*16 + 8) * 36 + aoffl + kg*8);
                af[mt][0] = lo.x; af[mt][1] = hi.x; af[mt][2] = lo.y; af[mt][3] = hi.y;
            }
            u32 bf[4][2];
#pragma unroll
            for (int nt = 0; nt < 4; nt++) {
                uint2 b2 = *(const uint2*)(Bb + (wn0 + nt*8) * 36 + aoffl + kg*8);
                bf[nt][0] = b2.x; bf[nt][1] = b2.y;
            }
#pragma unroll
            for (int mt = 0; mt < 2; mt++)
#pragma unroll
                for (int nt = 0; nt < 4; nt++)
                    mma_tf32(acc[mt][nt], af[mt], bf[nt]);
        }
    }

    // epilogue: C frag m16n8: (d0,d1) row l>>2 cols 2c,2c+1; (d2,d3) row+8
#pragma unroll
    for (int mt = 0; mt < 2; mt++) {
        int row = m0 + wm0 + mt * 16 + (lane >> 2);
#pragma unroll
        for (int nt = 0; nt < 4; nt++) {
            int nl = wn0 + nt * 8 + (lane & 3) * 2;
            float b0 = bsm[nl], b1 = bsm[nl + 1];
            *(float2*)&g_gi[row * GI_COLS + n0 + nl] =
                make_float2(acc[mt][nt][0] + b0, acc[mt][nt][1] + b1);
            *(float2*)&g_gi[(row + 8) * GI_COLS + n0 + nl] =
                make_float2(acc[mt][nt][2] + b0, acc[mt][nt][3] + b1);
        }
    }
    #undef STAGE
    #undef PA
    #undef PB
}

// ---------------------------------------------------------------------------
// Kernel A: gates + hnext + logit.  blockIdx.y = template t. (unchanged)
// ---------------------------------------------------------------------------
#define PT 192
__global__ void __launch_bounds__(PT, 2) gates_kernel(
    const float* __restrict__ h,
    const float* __restrict__ W_hh,
    const float* __restrict__ b_hh,
    const float* __restrict__ w_read,
    const float* __restrict__ w_write)
{
    __shared__ float Wg[96 * 32];
    __shared__ float Ww[32 * 16];
    __shared__ float Wr[32 * 16];
    __shared__ float bs[96];

    const int tid = threadIdx.x;
    const int t   = blockIdx.y;

    {
        const float4* s1 = (const float4*)(W_hh + t * 96 * 32);
        float4* d1 = (float4*)Wg;
        for (int i = tid; i < 768; i += PT) d1[i] = s1[i];
        if (tid < 128) ((float4*)Ww)[tid] = ((const float4*)(w_write + t * 512))[tid];
        if (tid < 128) ((float4*)Wr)[tid] = ((const float4*)w_read)[tid];
        if (tid < 24)  ((float4*)bs)[tid] = ((const float4*)(b_hh + t * 96))[tid];
    }
    __syncthreads();

    const int p = blockIdx.x * PT + tid;
    if (p >= NPAIR) return;
    const int b  = p >> 3;
    const int n1 = b * 16 + (p & 7);
    const int n2 = n1 + 8;

    u64 hA[16], hB[16];
    {
        const ulonglong2* h1 = (const ulonglong2*)(h + n1 * MM);
        const ulonglong2* h2 = (const ulonglong2*)(h + n2 * MM);
#pragma unroll
        for (int q = 0; q < 8; q++) {
            ulonglong2 v = h1[q]; hA[2*q] = v.x; hA[2*q+1] = v.y;
            ulonglong2 w = h2[q]; hB[2*q] = w.x; hB[2*q+1] = w.y;
        }
    }

    u64 hrA[8], hrB[8];
#pragma unroll
    for (int i = 0; i < 8; i++) { hrA[i] = 0ull; hrB[i] = 0ull; }
#pragma unroll 4
    for (int m = 0; m < 32; m++) {
        const ulonglong2* w = (const ulonglong2*)(Wr + m * 16);
        ulonglong2 w0 = w[0], w1 = w[1], w2 = w[2], w3 = w[3];
        float lo, hi;
        unpk(lo, hi, hA[m >> 1]); float ha = (m & 1) ? hi : lo;
        unpk(lo, hi, hB[m >> 1]); float hb = (m & 1) ? hi : lo;
        u64 dA = pk(ha, ha), dB = pk(hb, hb);
        fma2(hrA[0], dA, w0.x); fma2(hrA[1], dA, w0.y);
        fma2(hrA[2], dA, w1.x); fma2(hrA[3], dA, w1.y);
        fma2(hrA[4], dA, w2.x); fma2(hrA[5], dA, w2.y);
        fma2(hrA[6], dA, w3.x); fma2(hrA[7], dA, w3.y);
        fma2(hrB[0], dB, w0.x); fma2(hrB[1], dB, w0.y);
        fma2(hrB[2], dB, w1.x); fma2(hrB[3], dB, w1.y);
        fma2(hrB[4], dB, w2.x); fma2(hrB[5], dB, w2.y);
        fma2(hrB[6], dB, w3.x); fma2(hrB[7], dB, w3.y);
    }

    const float* gib = g_gi + b * GI_COLS + t * 96;
    float* ho1 = g_hn + (t * (size_t)NTOT + n1) * MM;
    float* ho2 = g_hn + (t * (size_t)NTOT + n2) * MM;
    float lg1 = 0.f, lg2 = 0.f;

#pragma unroll 1
    for (int l4 = 0; l4 < 8; l4++) {
        float Ga[4], Gb[4], Gc[4];
        *(float4*)Ga = *(const float4*)(gib + 4*l4);
        *(float4*)Gb = *(const float4*)(gib + 32 + 4*l4);
        *(float4*)Gc = *(const float4*)(gib + 64 + 4*l4);
        float o1[4], o2[4];
#pragma unroll
        for (int li = 0; li < 4; li++) {
            const int l = 4*l4 + li;
            const ulonglong2* wr = (const ulonglong2*)(Wg + l * 32);
            const ulonglong2* wz = (const ulonglong2*)(Wg + (32 + l) * 32);
            const ulonglong2* wn = (const ulonglong2*)(Wg + (64 + l) * 32);
            u64 aR1 = pk(bs[l],      0.f), aR2 = aR1;
            u64 aZ1 = pk(bs[32 + l], 0.f), aZ2 = aZ1;
            u64 aN1 = pk(bs[64 + l], 0.f), aN2 = aN1;
#pragma unroll
            for (int q = 0; q < 8; q++) {
                ulonglong2 wa = wr[q];
                fma2(aR1, wa.x, hA[2*q]); fma2(aR1, wa.y, hA[2*q+1]);
                fma2(aR2, wa.x, hB[2*q]); fma2(aR2, wa.y, hB[2*q+1]);
            }
#pragma unroll
            for (int q = 0; q < 8; q++) {
                ulonglong2 wb = wz[q];
                fma2(aZ1, wb.x, hA[2*q]); fma2(aZ1, wb.y, hA[2*q+1]);
                fma2(aZ2, wb.x, hB[2*q]); fma2(aZ2, wb.y, hB[2*q+1]);
            }
#pragma unroll
            for (int q = 0; q < 8; q++) {
                ulonglong2 wc = wn[q];
                fma2(aN1, wc.x, hA[2*q]); fma2(aN1, wc.y, hA[2*q+1]);
                fma2(aN2, wc.x, hB[2*q]); fma2(aN2, wc.y, hB[2*q+1]);
            }
            const ulonglong2* ww = (const ulonglong2*)(Ww + l * 16);
            ulonglong2 w0 = ww[0], w1 = ww[1], w2 = ww[2], w3 = ww[3];
            u64 aA1 = 0ull, aA2 = 0ull;
            fma2(aA1, w0.x, hrA[0]); fma2(aA1, w0.y, hrA[1]);
            fma2(aA1, w1.x, hrA[2]); fma2(aA1, w1.y, hrA[3]);
            fma2(aA1, w2.x, hrA[4]); fma2(aA1, w2.y, hrA[5]);
            fma2(aA1, w3.x, hrA[6]); fma2(aA1, w3.y, hrA[7]);
            fma2(aA2, w0.x, hrB[0]); fma2(aA2, w0.y, hrB[1]);
            fma2(aA2, w1.x, hrB[2]); fma2(aA2, w1.y, hrB[3]);
            fma2(aA2, w2.x, hrB[4]); fma2(aA2, w2.y, hrB[5]);
            fma2(aA2, w3.x, hrB[6]); fma2(aA2, w3.y, hrB[7]);

            {
                float ar = hadd(aR1), az = hadd(aZ1), an = hadd(aN1), av = hadd(aA1);
                float lo, hi; unpk(lo, hi, hA[l >> 1]); float hl = (l & 1) ? hi : lo;
                float r  = __fdividef(1.f, 1.f + __expf(-(Ga[li] + ar)));
                float z  = __fdividef(1.f, 1.f + __expf(-(Gb[li] + az)));
                float xn = Gc[li] + r * an;
                float e2 = __expf(-2.f * xn);
                float nn = __fdividef(1.f - e2, 1.f + e2);
                float hn = (1.f - z) * nn + z * hl;
                o1[li] = hn;
                lg1 = fmaf(hn, av, lg1);
            }
            {
                float ar = hadd(aR2), az = hadd(aZ2), an = hadd(aN2), av = hadd(aA2);
                float lo, hi; unpk(lo, hi, hB[l >> 1]); float hl = (l & 1) ? hi : lo;
                float r  = __fdividef(1.f, 1.f + __expf(-(Ga[li] + ar)));
                float z  = __fdividef(1.f, 1.f + __expf(-(Gb[li] + az)));
                float xn = Gc[li] + r * an;
                float e2 = __expf(-2.f * xn);
                float nn = __fdividef(1.f - e2, 1.f + e2);
                float hn = (1.f - z) * nn + z * hl;
                o2[li] = hn;
                lg2 = fmaf(hn, av, lg2);
            }
        }
        *(float4*)(ho1 + 4*l4) = *(float4*)o1;
        *(float4*)(ho2 + 4*l4) = *(float4*)o2;
    }
    g_lg[n1 * TT + t] = lg1;
    g_lg[n2 * TT + t] = lg2;
}

// ---------------------------------------------------------------------------
// Kernel B: gumbel softmax + hard select + gather + outputs (unchanged)
// ---------------------------------------------------------------------------
__global__ void __launch_bounds__(256) select_kernel(
    const float* __restrict__ gum,
    float* __restrict__ out)
{
    const int n = blockIdx.x * 256 + threadIdx.x;

    float s[8];
    {
        const float4* lp = (const float4*)(g_lg + n * TT);
        const float4* gp = (const float4*)(gum + n * TT);
        float4 l0 = lp[0], l1 = lp[1], g0 = gp[0], g1 = gp[1];
        s[0] = (l0.x + g0.x) * 2.f; s[1] = (l0.y + g0.y) * 2.f;
        s[2] = (l0.z + g0.z) * 2.f; s[3] = (l0.w + g0.w) * 2.f;
        s[4] = (l1.x + g1.x) * 2.f; s[5] = (l1.y + g1.y) * 2.f;
        s[6] = (l1.z + g1.z) * 2.f; s[7] = (l1.w + g1.w) * 2.f;
    }
    float smax = s[0];
    int amax = 0;
#pragma unroll
    for (int t = 1; t < 8; t++)
        if (s[t] > smax) { smax = s[t]; amax = t; }
    float sum = 0.f;
#pragma unroll
    for (int t = 0; t < 8; t++) sum += __expf(s[t] - smax);

    float p = __fdividef(1.f, sum);
    float attv = (1.f + p) - p;

    const float4* hp = (const float4*)(g_hn + (amax * (size_t)NTOT + n) * MM);
    float4* ho = (float4*)(out + n * MM);
#pragma unroll
    for (int i = 0; i < 8; i++) {
        float4 v = hp[i];
        v.x *= attv; v.y *= attv; v.z *= attv; v.w *= attv;
        ho[i] = v;
    }
    float* ao = out + BS * NHID + n * TT;
#pragma unroll
    for (int t = 0; t < 8; t++) ao[t] = (t == amax) ? attv : 0.f;
}

// ---------------------------------------------------------------------------
extern "C" void kernel_launch(void* const* d_in, const int* in_sizes, int n_in,
                              void* d_out, int out_size)
{
    const float* x       = (const float*)d_in[0];
    const float* h       = (const float*)d_in[1];
    const float* W_ih    = (const float*)d_in[2];
    const float* W_hh    = (const float*)d_in[3];
    const float* b_ih    = (const float*)d_in[4];
    const float* b_hh    = (const float*)d_in[5];
    const float* w_read  = (const float*)d_in[6];
    const float* w_write = (const float*)d_in[7];
    const float* gum     = (const float*)d_in[8];
    float* out = (float*)d_out;

    float* xs_ptr; cudaGetSymbolAddress((void**)&xs_ptr, g_xs);
    float* ws_ptr; cudaGetSymbolAddress((void**)&ws_ptr, g_ws);

    // split + permute x and W_ih into tf32 planes
    convert_split_kernel<<<(BS * 64 + 255) / 256, 256>>>(x, xs_ptr, XSTR, BS * 64);
    convert_split_kernel<<<(GI_COLS * 64 + 255) / 256, 256>>>(W_ih, ws_ptr, WSTR, GI_COLS * 64);

    // tensor-core gi GEMM (triple-buffered pipeline)
    cudaFuncSetAttribute(mma_gi_kernel,
                         cudaFuncAttributeMaxDynamicSharedMemorySize, GSM);
    dim3 g1(GI_COLS / 64, BS / 64);                  // (12, 32)
    mma_gi_kernel<<<g1, 128, GSM>>>(b_ih);

    dim3 g2((NPAIR + PT - 1) / PT, TT);              // (86, 8)
    gates_kernel<<<g2, PT>>>(h, W_hh, b_hh, w_read, w_write);

    select_kernel<<<NTOT / 256, 256>>>(gum, out);
}

// round 11
// speedup vs baseline: 1.5458x; 1.5458x over previous
#include <cuda_runtime.h>

#define BS    2048
#define NINP  512
#define NHID  512
#define TT    8
#define MM    32
#define NTOT  32768
#define GI_COLS 768
#define NPAIR (NTOT/2)   // 16384
#define KSPLIT 4

typedef unsigned long long u64;
typedef unsigned int u32;

// device scratch
__device__ float g_gi[BS * GI_COLS];            // 6 MB
__device__ float g_gip[KSPLIT][BS * GI_COLS];   // gemm partials, 25 MB
__device__ float g_hn[TT * NTOT * MM];          // hnext, 32 MB
__device__ float g_lg[NTOT * TT];               // logits, 1 MB
__device__ float g_hr[NTOT * 16];               // h_read, 2 MB

// ---- packed f32x2 helpers --------------------------------------------------
__device__ __forceinline__ void fma2(u64& acc, u64 a, u64 b) {
    asm("fma.rn.f32x2 %0, %1, %2, %0;" : "+l"(acc) : "l"(a), "l"(b));
}
__device__ __forceinline__ u64 pk(float lo, float hi) {
    u64 r; asm("mov.b64 %0, {%1, %2};" : "=l"(r) : "f"(lo), "f"(hi)); return r;
}
__device__ __forceinline__ void unpk(float& lo, float& hi, u64 v) {
    asm("mov.b64 {%0, %1}, %2;" : "=f"(lo), "=f"(hi) : "l"(v));
}
__device__ __forceinline__ float hadd(u64 v) {
    float a, b; unpk(a, b, v); return a + b;
}

// ---------------------------------------------------------------------------
// Kernel 1: gi partials = x @ W_ih^T (k-split by 4).
// Tile 128m x 64n, 128 threads (ty=tid>>3 [16], tx=tid&7 [8]), 8m x 8n per
// thread, m-paired FFMA2. Smem [k][m]/[k][n] (DYNAMIC, 50 KB), conflict-free
// frag loads. Reg-prefetch double buffer.
// ---------------------------------------------------------------------------
#define SA 132          // As row stride (128 m + pad), 528B % 16 == 0
#define SB 68           // Bs row stride (64 n + pad)
#define GEMM_SMEM ((2 * 32 * SA + 2 * 32 * SB) * 4)   // 51200 B

__global__ void __launch_bounds__(128, 3) gemm_gi_kernel(
    const float* __restrict__ A,        // x [2048][512]
    const float* __restrict__ B)        // W_ih [768][512]
{
    extern __shared__ float smem[];
    float* Asm = smem;                  // [2][32*SA]
    float* Bsm = smem + 2 * 32 * SA;    // [2][32*SB]

    const int tid = threadIdx.x;
    const int tx  = tid & 7;
    const int ty  = tid >> 3;
    const int n0  = blockIdx.x * 64;
    const int m0  = blockIdx.y * 128;
    const int ks  = blockIdx.z;
    const int kb0 = ks * 128;

    float4 ra[8], rb[4];

    #define LDG_CHUNK(c) {                                                    \
        const int kb_ = kb0 + (c) * 32;                                       \
        _Pragma("unroll")                                                     \
        for (int i_ = 0; i_ < 8; i_++) {                                      \
            int idx_ = tid + 128 * i_;                                        \
            ra[i_] = *(const float4*)&A[(m0 + (idx_ >> 3)) * NINP + kb_ + (idx_ & 7) * 4]; \
        }                                                                     \
        _Pragma("unroll")                                                     \
        for (int i_ = 0; i_ < 4; i_++) {                                      \
            int idx_ = tid + 128 * i_;                                        \
            rb[i_] = *(const float4*)&B[(n0 + (idx_ >> 3)) * NINP + kb_ + (idx_ & 7) * 4]; \
        }                                                                     \
    }

    #define STS_CHUNK(buf) {                                                  \
        _Pragma("unroll")                                                     \
        for (int i_ = 0; i_ < 8; i_++) {                                      \
            int idx_ = tid + 128 * i_;                                        \
            int r_ = idx_ >> 3, kc_ = (idx_ & 7) * 4;                         \
            Asm[(buf) * 32 * SA + (kc_ + 0) * SA + r_] = ra[i_].x;            \
            Asm[(buf) * 32 * SA + (kc_ + 1) * SA + r_] = ra[i_].y;            \
            Asm[(buf) * 32 * SA + (kc_ + 2) * SA + r_] = ra[i_].z;            \
            Asm[(buf) * 32 * SA + (kc_ + 3) * SA + r_] = ra[i_].w;            \
        }                                                                     \
        _Pragma("unroll")                                                     \
        for (int i_ = 0; i_ < 4; i_++) {                                      \
            int idx_ = tid + 128 * i_;                                        \
            int r_ = idx_ >> 3, kc_ = (idx_ & 7) * 4;                         \
            Bsm[(buf) * 32 * SB + (kc_ + 0) * SB + r_] = rb[i_].x;            \
            Bsm[(buf) * 32 * SB + (kc_ + 1) * SB + r_] = rb[i_].y;            \
            Bsm[(buf) * 32 * SB + (kc_ + 2) * SB + r_] = rb[i_].z;            \
            Bsm[(buf) * 32 * SB + (kc_ + 3) * SB + r_] = rb[i_].w;            \
        }                                                                     \
    }

    u64 acc[4][8];                    // 4 m-pairs x 8 n
#pragma unroll
    for (int i = 0; i < 4; i++)
#pragma unroll
        for (int j = 0; j < 8; j++) acc[i][j] = 0ull;

    LDG_CHUNK(0);
    STS_CHUNK(0);
    LDG_CHUNK(1);
    __syncthreads();

#pragma unroll 1
    for (int c = 0; c < 4; c++) {
        const int buf = c & 1;
        if (c < 3) STS_CHUNK(buf ^ 1);
        if (c < 2) LDG_CHUNK(c + 2);

        const float* Ab = Asm + buf * 32 * SA;
        const float* Bb = Bsm + buf * 32 * SB;
#pragma unroll
        for (int k = 0; k < 32; k++) {
            ulonglong2 a1 = *(const ulonglong2*)(Ab + k * SA + ty * 4);
            ulonglong2 a2 = *(const ulonglong2*)(Ab + k * SA + 64 + ty * 4);
            float4 b1 = *(const float4*)(Bb + k * SB + tx * 4);
            float4 b2 = *(const float4*)(Bb + k * SB + 32 + tx * 4);
            u64 bb[8];
            bb[0] = pk(b1.x, b1.x); bb[1] = pk(b1.y, b1.y);
            bb[2] = pk(b1.z, b1.z); bb[3] = pk(b1.w, b1.w);
            bb[4] = pk(b2.x, b2.x); bb[5] = pk(b2.y, b2.y);
            bb[6] = pk(b2.z, b2.z); bb[7] = pk(b2.w, b2.w);
#pragma unroll
            for (int j = 0; j < 8; j++) {
                fma2(acc[0][j], a1.x, bb[j]);
                fma2(acc[1][j], a1.y, bb[j]);
                fma2(acc[2][j], a2.x, bb[j]);
                fma2(acc[3][j], a2.y, bb[j]);
            }
        }
        __syncthreads();
    }

    // epilogue: unpack m-pairs -> per-m float4 rows, write partial
    float* gp = g_gip[ks];
#pragma unroll
    for (int mp = 0; mp < 4; mp++) {
        int mrow = m0 + ((mp < 2) ? (ty * 4 + mp * 2) : (64 + ty * 4 + (mp - 2) * 2));
        float lo[8], hi[8];
#pragma unroll
        for (int j = 0; j < 8; j++) unpk(lo[j], hi[j], acc[mp][j]);
        *(float4*)&gp[mrow * GI_COLS + n0 + tx * 4] =
            make_float4(lo[0], lo[1], lo[2], lo[3]);
        *(float4*)&gp[mrow * GI_COLS + n0 + 32 + tx * 4] =
            make_float4(lo[4], lo[5], lo[6], lo[7]);
        *(float4*)&gp[(mrow + 1) * GI_COLS + n0 + tx * 4] =
            make_float4(hi[0], hi[1], hi[2], hi[3]);
        *(float4*)&gp[(mrow + 1) * GI_COLS + n0 + 32 + tx * 4] =
            make_float4(hi[4], hi[5], hi[6], hi[7]);
    }
    #undef LDG_CHUNK
    #undef STS_CHUNK
}

// ---------------------------------------------------------------------------
// Kernel 1b: reduce partials + bias -> g_gi
// ---------------------------------------------------------------------------
__global__ void __launch_bounds__(256) reduce_gi_kernel(
    const float* __restrict__ bias)
{
    int i = blockIdx.x * 256 + threadIdx.x;          // float4 index
    int col = (i * 4) % GI_COLS;
    float4 b = *(const float4*)&bias[col];
    float4 s0 = *(const float4*)&g_gip[0][i * 4];
    float4 s1 = *(const float4*)&g_gip[1][i * 4];
    float4 s2 = *(const float4*)&g_gip[2][i * 4];
    float4 s3 = *(const float4*)&g_gip[3][i * 4];
    float4 r;
    r.x = ((s0.x + s1.x) + (s2.x + s3.x)) + b.x;
    r.y = ((s0.y + s1.y) + (s2.y + s3.y)) + b.y;
    r.z = ((s0.z + s1.z) + (s2.z + s3.z)) + b.z;
    r.w = ((s0.w + s1.w) + (s2.w + s3.w)) + b.w;
    *(float4*)&g_gi[i * 4] = r;
}

// ---------------------------------------------------------------------------
// Kernel 1c: h_read per n (computed once, not 8x).
// ---------------------------------------------------------------------------
__global__ void __launch_bounds__(256) hr_kernel(
    const float* __restrict__ h,
    const float* __restrict__ w_read)
{
    __shared__ float Wr[512];
    const int tid = threadIdx.x;
    if (tid < 128) ((float4*)Wr)[tid] = ((const float4*)w_read)[tid];
    __syncthreads();

    const int n = blockIdx.x * 256 + tid;
    float h2[32];
    {
        const float4* hp = (const float4*)(h + n * MM);
#pragma unroll
        for (int i = 0; i < 8; i++) {
            float4 v = hp[i];
            h2[4*i] = v.x; h2[4*i+1] = v.y; h2[4*i+2] = v.z; h2[4*i+3] = v.w;
        }
    }
    float hr[16];
#pragma unroll
    for (int f = 0; f < 16; f++) hr[f] = 0.f;
#pragma unroll 4
    for (int m = 0; m < 32; m++) {
        const float4* w = (const float4*)(Wr + m * 16);
        float hm = h2[m];
#pragma unroll
        for (int f4 = 0; f4 < 4; f4++) {
            float4 v = w[f4];
            hr[4*f4]   = fmaf(hm, v.x, hr[4*f4]);
            hr[4*f4+1] = fmaf(hm, v.y, hr[4*f4+1]);
            hr[4*f4+2] = fmaf(hm, v.z, hr[4*f4+2]);
            hr[4*f4+3] = fmaf(hm, v.w, hr[4*f4+3]);
        }
    }
    float4* d = (float4*)(g_hr + n * 16);
#pragma unroll
    for (int f4 = 0; f4 < 4; f4++)
        d[f4] = make_float4(hr[4*f4], hr[4*f4+1], hr[4*f4+2], hr[4*f4+3]);
}

// ---------------------------------------------------------------------------
// Kernel A: gates + hnext + logit.  blockIdx.y = template t.
// (round-7 verified structure; hr loaded from g_hr)
// ---------------------------------------------------------------------------
#define PT 192
__global__ void __launch_bounds__(PT, 2) gates_kernel(
    const float* __restrict__ h,
    const float* __restrict__ W_hh,
    const float* __restrict__ b_hh,
    const float* __restrict__ w_write)
{
    __shared__ float Wg[96 * 32];
    __shared__ float Ww[32 * 16];
    __shared__ float bs[96];

    const int tid = threadIdx.x;
    const int t   = blockIdx.y;

    {
        const float4* s1 = (const float4*)(W_hh + t * 96 * 32);
        float4* d1 = (float4*)Wg;
        for (int i = tid; i < 768; i += PT) d1[i] = s1[i];
        if (tid < 128) ((float4*)Ww)[tid] = ((const float4*)(w_write + t * 512))[tid];
        if (tid < 24)  ((float4*)bs)[tid] = ((const float4*)(b_hh + t * 96))[tid];
    }
    __syncthreads();

    const int p = blockIdx.x * PT + tid;
    if (p >= NPAIR) return;
    const int b  = p >> 3;
    const int n1 = b * 16 + (p & 7);
    const int n2 = n1 + 8;

    u64 hA[16], hB[16];
    {
        const ulonglong2* h1 = (const ulonglong2*)(h + n1 * MM);
        const ulonglong2* h2 = (const ulonglong2*)(h + n2 * MM);
#pragma unroll
        for (int q = 0; q < 8; q++) {
            ulonglong2 v = h1[q]; hA[2*q] = v.x; hA[2*q+1] = v.y;
            ulonglong2 w = h2[q]; hB[2*q] = w.x; hB[2*q+1] = w.y;
        }
    }

    // h_read from precomputed g_hr (packed into f-pairs)
    u64 hrA[8], hrB[8];
    {
        const float4* r1 = (const float4*)(g_hr + n1 * 16);
        const float4* r2 = (const float4*)(g_hr + n2 * 16);
#pragma unroll
        for (int q = 0; q < 4; q++) {
            float4 v = r1[q];
            hrA[2*q]   = pk(v.x, v.y);
            hrA[2*q+1] = pk(v.z, v.w);
            float4 w = r2[q];
            hrB[2*q]   = pk(w.x, w.y);
            hrB[2*q+1] = pk(w.z, w.w);
        }
    }

    const float* gib = g_gi + b * GI_COLS + t * 96;
    float* ho1 = g_hn + (t * (size_t)NTOT + n1) * MM;
    float* ho2 = g_hn + (t * (size_t)NTOT + n2) * MM;
    float lg1 = 0.f, lg2 = 0.f;

#pragma unroll 1
    for (int l4 = 0; l4 < 8; l4++) {
        float Ga[4], Gb[4], Gc[4];
        *(float4*)Ga = *(const float4*)(gib + 4*l4);
        *(float4*)Gb = *(const float4*)(gib + 32 + 4*l4);
        *(float4*)Gc = *(const float4*)(gib + 64 + 4*l4);
        float o1[4], o2[4];
#pragma unroll
        for (int li = 0; li < 4; li++) {
            const int l = 4*l4 + li;
            const ulonglong2* wr = (const ulonglong2*)(Wg + l * 32);
            const ulonglong2* wz = (const ulonglong2*)(Wg + (32 + l) * 32);
            const ulonglong2* wn = (const ulonglong2*)(Wg + (64 + l) * 32);
            u64 aR1 = pk(bs[l],      0.f), aR2 = aR1;
            u64 aZ1 = pk(bs[32 + l], 0.f), aZ2 = aZ1;
            u64 aN1 = pk(bs[64 + l], 0.f), aN2 = aN1;
#pragma unroll
            for (int q = 0; q < 8; q++) {
                ulonglong2 wa = wr[q];
                fma2(aR1, wa.x, hA[2*q]); fma2(aR1, wa.y, hA[2*q+1]);
                fma2(aR2, wa.x, hB[2*q]); fma2(aR2, wa.y, hB[2*q+1]);
            }
#pragma unroll
            for (int q = 0; q < 8; q++) {
                ulonglong2 wb = wz[q];
                fma2(aZ1, wb.x, hA[2*q]); fma2(aZ1, wb.y, hA[2*q+1]);
                fma2(aZ2, wb.x, hB[2*q]); fma2(aZ2, wb.y, hB[2*q+1]);
            }
#pragma unroll
            for (int q = 0; q < 8; q++) {
                ulonglong2 wc = wn[q];
                fma2(aN1, wc.x, hA[2*q]); fma2(aN1, wc.y, hA[2*q+1]);
                fma2(aN2, wc.x, hB[2*q]); fma2(aN2, wc.y, hB[2*q+1]);
            }
            const ulonglong2* ww = (const ulonglong2*)(Ww + l * 16);
            ulonglong2 w0 = ww[0], w1 = ww[1], w2 = ww[2], w3 = ww[3];
            u64 aA1 = 0ull, aA2 = 0ull;
            fma2(aA1, w0.x, hrA[0]); fma2(aA1, w0.y, hrA[1]);
            fma2(aA1, w1.x, hrA[2]); fma2(aA1, w1.y, hrA[3]);
            fma2(aA1, w2.x, hrA[4]); fma2(aA1, w2.y, hrA[5]);
            fma2(aA1, w3.x, hrA[6]); fma2(aA1, w3.y, hrA[7]);
            fma2(aA2, w0.x, hrB[0]); fma2(aA2, w0.y, hrB[1]);
            fma2(aA2, w1.x, hrB[2]); fma2(aA2, w1.y, hrB[3]);
            fma2(aA2, w2.x, hrB[4]); fma2(aA2, w2.y, hrB[5]);
            fma2(aA2, w3.x, hrB[6]); fma2(aA2, w3.y, hrB[7]);

            {
                float ar = hadd(aR1), az = hadd(aZ1), an = hadd(aN1), av = hadd(aA1);
                float lo, hi; unpk(lo, hi, hA[l >> 1]); float hl = (l & 1) ? hi : lo;
                float r  = __fdividef(1.f, 1.f + __expf(-(Ga[li] + ar)));
                float z  = __fdividef(1.f, 1.f + __expf(-(Gb[li] + az)));
                float xn = Gc[li] + r * an;
                float e2 = __expf(-2.f * xn);
                float nn = __fdividef(1.f - e2, 1.f + e2);
                float hn = (1.f - z) * nn + z * hl;
                o1[li] = hn;
                lg1 = fmaf(hn, av, lg1);
            }
            {
                float ar = hadd(aR2), az = hadd(aZ2), an = hadd(aN2), av = hadd(aA2);
                float lo, hi; unpk(lo, hi, hB[l >> 1]); float hl = (l & 1) ? hi : lo;
                float r  = __fdividef(1.f, 1.f + __expf(-(Ga[li] + ar)));
                float z  = __fdividef(1.f, 1.f + __expf(-(Gb[li] + az)));
                float xn = Gc[li] + r * an;
                float e2 = __expf(-2.f * xn);
                float nn = __fdividef(1.f - e2, 1.f + e2);
                float hn = (1.f - z) * nn + z * hl;
                o2[li] = hn;
                lg2 = fmaf(hn, av, lg2);
            }
        }
        *(float4*)(ho1 + 4*l4) = *(float4*)o1;
        *(float4*)(ho2 + 4*l4) = *(float4*)o2;
    }
    g_lg[n1 * TT + t] = lg1;
    g_lg[n2 * TT + t] = lg2;
}

// ---------------------------------------------------------------------------
// Kernel B: gumbel softmax + hard select + gather + outputs (unchanged)
// ---------------------------------------------------------------------------
__global__ void __launch_bounds__(256) select_kernel(
    const float* __restrict__ gum,
    float* __restrict__ out)
{
    const int n = blockIdx.x * 256 + threadIdx.x;

    float s[8];
    {
        const float4* lp = (const float4*)(g_lg + n * TT);
        const float4* gp = (const float4*)(gum + n * TT);
        float4 l0 = lp[0], l1 = lp[1], g0 = gp[0], g1 = gp[1];
        s[0] = (l0.x + g0.x) * 2.f; s[1] = (l0.y + g0.y) * 2.f;
        s[2] = (l0.z + g0.z) * 2.f; s[3] = (l0.w + g0.w) * 2.f;
        s[4] = (l1.x + g1.x) * 2.f; s[5] = (l1.y + g1.y) * 2.f;
        s[6] = (l1.z + g1.z) * 2.f; s[7] = (l1.w + g1.w) * 2.f;
    }
    float smax = s[0];
    int amax = 0;
#pragma unroll
    for (int t = 1; t < 8; t++)
        if (s[t] > smax) { smax = s[t]; amax = t; }
    float sum = 0.f;
#pragma unroll
    for (int t = 0; t < 8; t++) sum += __expf(s[t] - smax);

    float p = __fdividef(1.f, sum);
    float attv = (1.f + p) - p;

    const float4* hp = (const float4*)(g_hn + (amax * (size_t)NTOT + n) * MM);
    float4* ho = (float4*)(out + n * MM);
#pragma unroll
    for (int i = 0; i < 8; i++) {
        float4 v = hp[i];
        v.x *= attv; v.y *= attv; v.z *= attv; v.w *= attv;
        ho[i] = v;
    }
    float* ao = out + BS * NHID + n * TT;
#pragma unroll
    for (int t = 0; t < 8; t++) ao[t] = (t == amax) ? attv : 0.f;
}

// ---------------------------------------------------------------------------
extern "C" void kernel_launch(void* const* d_in, const int* in_sizes, int n_in,
                              void* d_out, int out_size)
{
    const float* x       = (const float*)d_in[0];
    const float* h       = (const float*)d_in[1];
    const float* W_ih    = (const float*)d_in[2];
    const float* W_hh    = (const float*)d_in[3];
    const float* b_ih    = (const float*)d_in[4];
    const float* b_hh    = (const float*)d_in[5];
    const float* w_read  = (const float*)d_in[6];
    const float* w_write = (const float*)d_in[7];
    const float* gum     = (const float*)d_in[8];
    float* out = (float*)d_out;

    // gi GEMM: k-split x4, fma2 (dynamic smem), then reduce(+bias)
    cudaFuncSetAttribute(gemm_gi_kernel,
                         cudaFuncAttributeMaxDynamicSharedMemorySize, GEMM_SMEM);
    dim3 g1(GI_COLS / 64, BS / 128, KSPLIT);          // (12, 16, 4) = 768
    gemm_gi_kernel<<<g1, 128, GEMM_SMEM>>>(x, W_ih);
    reduce_gi_kernel<<<BS * GI_COLS / 4 / 256, 256>>>(b_ih);

    // h_read precompute
    hr_kernel<<<NTOT / 256, 256>>>(h, w_read);

    dim3 g2((NPAIR + PT - 1) / PT, TT);               // (86, 8)
    gates_kernel<<<g2, PT>>>(h, W_hh, b_hh, w_write);

    select_kernel<<<NTOT / 256, 256>>>(gum, out);
}